// round 5
// baseline (speedup 1.0000x reference)
#include <cuda_runtime.h>
#include <cstdint>

// DepthDCOp: out[n,c,h,w] = sum_{kh,kw} x_pad[n,c,h+kh-1,w+kw-1] * ker[n,0,kh*3+kw,h,w]
// N=8, C=256, H=64, W=64, K=3, dilation=1.

#define N_ 8
#define C_ 256
#define H_ 64
#define W_ 64
#define HW_ (H_ * W_)
#define CPT 2   // channels per thread

__global__ __launch_bounds__(256, 4)
void ddf_kernel(const float* __restrict__ x,
                const float* __restrict__ ker,
                float* __restrict__ out)
{
    // grid.x = N*H (one (n,h) row per block), grid.y = C/(16*CPT) = 8
    const int nh = blockIdx.x;
    const int n  = nh >> 6;          // / H_
    const int h  = nh & 63;          // % H_
    const int tx = threadIdx.x;      // 0..15 -> w quad
    const int ty = threadIdx.y;      // 0..15 -> channel pair
    const int tid = ty * 16 + tx;

    // Stage the 9 per-pixel kernel rows for this (n,h): 2.25 KB, read from
    // DRAM/L2 once per block, reused by 32 channels.
    __shared__ float sk[9][W_];
    {
        const float4* kp = reinterpret_cast<const float4*>(
            ker + (size_t)n * 9 * HW_ + (size_t)h * W_);
        if (tid < 144) {
            const int t = tid >> 4;
            const int q = tid & 15;
            reinterpret_cast<float4*>(&sk[t][0])[q] = kp[(size_t)t * (HW_ / 4) + q];
        }
    }
    __syncthreads();

    const int w0 = tx << 2;
    const int c0 = (blockIdx.y << 5) + (ty << 1);   // 2 channels per thread
    const bool up_ok   = (h > 0);
    const bool down_ok = (h < H_ - 1);
    const bool lok     = (tx > 0);
    const bool rok     = (tx < 15);

    const float* xb = x + (((size_t)n * C_ + c0) * H_ + h) * W_ + w0;
    const float4 z4 = make_float4(0.f, 0.f, 0.f, 0.f);

    // ---- All 18 loads independent & front-batched (6x LDG.128 + 12x LDG.32) ----
    float4 b[CPT][3];
    float  lh[CPT][3], rh[CPT][3];
    #pragma unroll
    for (int ci = 0; ci < CPT; ci++) {
        const float* p = xb + (size_t)ci * HW_;
        #pragma unroll
        for (int r = 0; r < 3; r++) {
            const float* pr = p + (r - 1) * W_;
            const bool rowok = (r == 1) | ((r == 0) ? up_ok : down_ok);
            b[ci][r]  = rowok         ? *reinterpret_cast<const float4*>(pr) : z4;
            lh[ci][r] = (rowok & lok) ? pr[-1] : 0.f;
            rh[ci][r] = (rowok & rok) ? pr[4]  : 0.f;
        }
    }

    // ---- 9 taps: one broadcast LDS.128 per tap, shared by both channels ----
    float acc[CPT][4];
    #pragma unroll
    for (int ci = 0; ci < CPT; ci++)
        #pragma unroll
        for (int j = 0; j < 4; j++) acc[ci][j] = 0.f;

    #pragma unroll
    for (int kh = 0; kh < 3; kh++) {
        #pragma unroll
        for (int kw = 0; kw < 3; kw++) {
            const float4 kvt =
                *reinterpret_cast<const float4*>(&sk[kh * 3 + kw][w0]);
            #pragma unroll
            for (int ci = 0; ci < CPT; ci++) {
                const float win[6] = { lh[ci][kh], b[ci][kh].x, b[ci][kh].y,
                                       b[ci][kh].z, b[ci][kh].w, rh[ci][kh] };
                acc[ci][0] = fmaf(kvt.x, win[kw + 0], acc[ci][0]);
                acc[ci][1] = fmaf(kvt.y, win[kw + 1], acc[ci][1]);
                acc[ci][2] = fmaf(kvt.z, win[kw + 2], acc[ci][2]);
                acc[ci][3] = fmaf(kvt.w, win[kw + 3], acc[ci][3]);
            }
        }
    }

    // ---- Stores ----
    float* ob = out + (((size_t)n * C_ + c0) * H_ + h) * W_ + w0;
    #pragma unroll
    for (int ci = 0; ci < CPT; ci++) {
        float4 o;
        o.x = acc[ci][0]; o.y = acc[ci][1]; o.z = acc[ci][2]; o.w = acc[ci][3];
        *reinterpret_cast<float4*>(ob + (size_t)ci * HW_) = o;
    }
}

extern "C" void kernel_launch(void* const* d_in, const int* in_sizes, int n_in,
                              void* d_out, int out_size)
{
    const float* x   = (const float*)d_in[0];   // [8,256,64,64]
    const float* ker = (const float*)d_in[1];   // [8,1,9,64,64]
    float* out = (float*)d_out;                 // [8,256,64,64]

    dim3 block(16, 16);
    dim3 grid(N_ * H_, C_ / (16 * CPT));
    ddf_kernel<<<grid, block>>>(x, ker, out);
}

// round 6
// speedup vs baseline: 1.3907x; 1.3907x over previous
#include <cuda_runtime.h>
#include <cstdint>

// DepthDCOp: out[n,c,h,w] = sum_{kh,kw} x_pad[n,c,h+kh-1,w+kw-1] * ker[n,0,kh*3+kw,h,w]
// N=8, C=256, H=64, W=64, K=3, dilation=1.

#define N_ 8
#define C_ 256
#define H_ 64
#define W_ 64
#define HW_ (H_ * W_)
#define CPT 2        // channels per thread
#define HSTRIP 8     // h rows per block

__global__ __launch_bounds__(256, 3)
void ddf_kernel(const float* __restrict__ x,
                const float* __restrict__ ker,
                float* __restrict__ out)
{
    // grid.x = N * (H/HSTRIP) = 64, grid.y = C/32 = 8  -> 512 blocks
    const int bx    = blockIdx.x;
    const int n     = bx >> 3;            // / (H_/HSTRIP)
    const int h0    = (bx & 7) * HSTRIP;
    const int tx    = threadIdx.x;        // 0..15 -> w quad
    const int ty    = threadIdx.y;        // 0..15 -> channel pair
    const int tid   = ty * 16 + tx;
    const int w0    = tx << 2;
    const int c0    = (blockIdx.y << 5) + (ty << 1);

    // ---- Stage ALL weights for this (n, h-strip): 8 x 9 x 64 floats = 18 KB ----
    __shared__ float4 sk[HSTRIP][9][16];   // [hh][tap][w-quad]
    {
        const float4* kp = reinterpret_cast<const float4*>(ker + (size_t)n * 9 * HW_);
        #pragma unroll
        for (int i = tid; i < HSTRIP * 9 * 16; i += 256) {
            const int hh  = i / 144;
            const int rem = i - hh * 144;
            const int t   = rem >> 4;
            const int q   = rem & 15;
            sk[hh][t][q] = kp[(size_t)t * (HW_ / 4) + (size_t)(h0 + hh) * 16 + q];
        }
    }

    const float* xb = x + (((size_t)n * C_ + c0) * H_) * W_ + w0;
    const float4 z4 = make_float4(0.f, 0.f, 0.f, 0.f);
    const bool lok = (tx > 0), rok = (tx < 15);

    // Row record: body float4 + halo scalars, for CPT channels.
    struct Row { float4 b[CPT]; float lh[CPT], rh[CPT]; };

    auto load_raw = [&](int hh, float4 raw[CPT]) {
        const bool ok = (hh >= 0) & (hh < H_);
        #pragma unroll
        for (int ci = 0; ci < CPT; ci++)
            raw[ci] = ok ? *reinterpret_cast<const float4*>(
                               xb + (size_t)ci * HW_ + (size_t)hh * W_)
                         : z4;
    };
    auto finish_row = [&](const float4 raw[CPT], Row& r) {
        #pragma unroll
        for (int ci = 0; ci < CPT; ci++) {
            r.b[ci]  = raw[ci];
            float l  = __shfl_up_sync(0xffffffffu,  raw[ci].w, 1, 16);
            float rr = __shfl_down_sync(0xffffffffu, raw[ci].x, 1, 16);
            r.lh[ci] = lok ? l  : 0.f;
            r.rh[ci] = rok ? rr : 0.f;
        }
    };

    // Prime the 3-row window: h0-1, h0, h0+1  (issue all LDGs before barrier).
    float4 raw0[CPT], raw1[CPT], raw2[CPT];
    load_raw(h0 - 1, raw0);
    load_raw(h0,     raw1);
    load_raw(h0 + 1, raw2);

    __syncthreads();   // weights staged; x loads above are in flight during the wait

    Row rbuf[3];
    finish_row(raw0, rbuf[0]);
    finish_row(raw1, rbuf[1]);
    finish_row(raw2, rbuf[2]);

    float* ob = out + (((size_t)n * C_ + c0) * H_ + h0) * W_ + w0;

    #pragma unroll
    for (int s = 0; s < HSTRIP; s++) {
        // Prefetch next row (LDG issued before this step's compute).
        float4 nxt[CPT];
        if (s < HSTRIP - 1) load_raw(h0 + s + 2, nxt);

        const Row& top = rbuf[ s      % 3];
        const Row& mid = rbuf[(s + 1) % 3];
        const Row& bot = rbuf[(s + 2) % 3];

        float acc[CPT][4];
        #pragma unroll
        for (int ci = 0; ci < CPT; ci++)
            #pragma unroll
            for (int j = 0; j < 4; j++) acc[ci][j] = 0.f;

        #pragma unroll
        for (int kh = 0; kh < 3; kh++) {
            const Row& rr = (kh == 0) ? top : (kh == 1) ? mid : bot;
            #pragma unroll
            for (int kw = 0; kw < 3; kw++) {
                const float4 kvt = sk[s][kh * 3 + kw][tx];
                #pragma unroll
                for (int ci = 0; ci < CPT; ci++) {
                    const float win[6] = { rr.lh[ci], rr.b[ci].x, rr.b[ci].y,
                                           rr.b[ci].z, rr.b[ci].w, rr.rh[ci] };
                    acc[ci][0] = fmaf(kvt.x, win[kw + 0], acc[ci][0]);
                    acc[ci][1] = fmaf(kvt.y, win[kw + 1], acc[ci][1]);
                    acc[ci][2] = fmaf(kvt.z, win[kw + 2], acc[ci][2]);
                    acc[ci][3] = fmaf(kvt.w, win[kw + 3], acc[ci][3]);
                }
            }
        }

        #pragma unroll
        for (int ci = 0; ci < CPT; ci++) {
            float4 o;
            o.x = acc[ci][0]; o.y = acc[ci][1]; o.z = acc[ci][2]; o.w = acc[ci][3];
            *reinterpret_cast<float4*>(ob + (size_t)ci * HW_ + (size_t)s * W_) = o;
        }

        // Rotate: finished prefetched row replaces the retired top slot.
        if (s < HSTRIP - 1) finish_row(nxt, rbuf[s % 3]);
    }
}

extern "C" void kernel_launch(void* const* d_in, const int* in_sizes, int n_in,
                              void* d_out, int out_size)
{
    const float* x   = (const float*)d_in[0];   // [8,256,64,64]
    const float* ker = (const float*)d_in[1];   // [8,1,9,64,64]
    float* out = (float*)d_out;                 // [8,256,64,64]

    dim3 block(16, 16);
    dim3 grid(N_ * (H_ / HSTRIP), C_ / (16 * CPT));
    ddf_kernel<<<grid, block>>>(x, ker, out);
}

// round 7
// speedup vs baseline: 1.4116x; 1.0151x over previous
#include <cuda_runtime.h>
#include <cstdint>

// DepthDCOp: out[n,c,h,w] = sum_{kh,kw} x_pad[n,c,h+kh-1,w+kw-1] * ker[n,0,kh*3+kw,h,w]
// N=8, C=256, H=64, W=64, K=3, dilation=1.

#define N_ 8
#define C_ 256
#define H_ 64
#define W_ 64
#define HW_ (H_ * W_)
#define CPT 2        // channels per thread
#define HSTRIP 8     // h rows per block

__global__ __launch_bounds__(256, 4)
void ddf_kernel(const float* __restrict__ x,
                const float* __restrict__ ker,
                float* __restrict__ out)
{
    // grid.x = N * (H/HSTRIP) = 64, grid.y = C/32 = 8  -> 512 blocks
    // 512 <= 148 SMs * 4 blocks  =>  single resident wave (no straggler tail).
    const int bx    = blockIdx.x;
    const int n     = bx >> 3;            // / (H_/HSTRIP)
    const int h0    = (bx & 7) * HSTRIP;
    const int tx    = threadIdx.x;        // 0..15 -> w quad
    const int ty    = threadIdx.y;        // 0..15 -> channel pair
    const int tid   = ty * 16 + tx;
    const int w0    = tx << 2;
    const int c0    = (blockIdx.y << 5) + (ty << 1);

    // ---- Stage ALL weights for this (n, h-strip): 8 x 9 x 64 floats = 18 KB ----
    __shared__ float4 sk[HSTRIP][9][16];   // [hh][tap][w-quad]
    {
        const float4* kp = reinterpret_cast<const float4*>(ker + (size_t)n * 9 * HW_);
        #pragma unroll
        for (int i = tid; i < HSTRIP * 9 * 16; i += 256) {
            const int hh  = i / 144;
            const int rem = i - hh * 144;
            const int t   = rem >> 4;
            const int q   = rem & 15;
            sk[hh][t][q] = kp[(size_t)t * (HW_ / 4) + (size_t)(h0 + hh) * 16 + q];
        }
    }

    const float* xb = x + (((size_t)n * C_ + c0) * H_) * W_ + w0;
    const float4 z4 = make_float4(0.f, 0.f, 0.f, 0.f);
    const bool lok = (tx > 0), rok = (tx < 15);

    // Row record: body float4 + halo scalars, for CPT channels.
    struct Row { float4 b[CPT]; float lh[CPT], rh[CPT]; };

    auto load_raw = [&](int hh, float4 raw[CPT]) {
        const bool ok = (hh >= 0) & (hh < H_);
        #pragma unroll
        for (int ci = 0; ci < CPT; ci++)
            raw[ci] = ok ? *reinterpret_cast<const float4*>(
                               xb + (size_t)ci * HW_ + (size_t)hh * W_)
                         : z4;
    };
    auto finish_row = [&](const float4 raw[CPT], Row& r) {
        #pragma unroll
        for (int ci = 0; ci < CPT; ci++) {
            r.b[ci]  = raw[ci];
            float l  = __shfl_up_sync(0xffffffffu,  raw[ci].w, 1, 16);
            float rr = __shfl_down_sync(0xffffffffu, raw[ci].x, 1, 16);
            r.lh[ci] = lok ? l  : 0.f;
            r.rh[ci] = rok ? rr : 0.f;
        }
    };

    // Prime the 3-row window: h0-1, h0, h0+1  (issue all LDGs before barrier).
    float4 raw0[CPT], raw1[CPT], raw2[CPT];
    load_raw(h0 - 1, raw0);
    load_raw(h0,     raw1);
    load_raw(h0 + 1, raw2);

    __syncthreads();   // weights staged; x loads above are in flight during the wait

    Row rbuf[3];
    finish_row(raw0, rbuf[0]);
    finish_row(raw1, rbuf[1]);
    finish_row(raw2, rbuf[2]);

    float* ob = out + (((size_t)n * C_ + c0) * H_ + h0) * W_ + w0;

    #pragma unroll
    for (int s = 0; s < HSTRIP; s++) {
        // Prefetch next row (LDG issued before this step's compute).
        float4 nxt[CPT];
        if (s < HSTRIP - 1) load_raw(h0 + s + 2, nxt);

        const Row& top = rbuf[ s      % 3];
        const Row& mid = rbuf[(s + 1) % 3];
        const Row& bot = rbuf[(s + 2) % 3];

        float acc[CPT][4];
        #pragma unroll
        for (int ci = 0; ci < CPT; ci++)
            #pragma unroll
            for (int j = 0; j < 4; j++) acc[ci][j] = 0.f;

        #pragma unroll
        for (int kh = 0; kh < 3; kh++) {
            const Row& rr = (kh == 0) ? top : (kh == 1) ? mid : bot;
            #pragma unroll
            for (int kw = 0; kw < 3; kw++) {
                const float4 kvt = sk[s][kh * 3 + kw][tx];
                #pragma unroll
                for (int ci = 0; ci < CPT; ci++) {
                    const float win[6] = { rr.lh[ci], rr.b[ci].x, rr.b[ci].y,
                                           rr.b[ci].z, rr.b[ci].w, rr.rh[ci] };
                    acc[ci][0] = fmaf(kvt.x, win[kw + 0], acc[ci][0]);
                    acc[ci][1] = fmaf(kvt.y, win[kw + 1], acc[ci][1]);
                    acc[ci][2] = fmaf(kvt.z, win[kw + 2], acc[ci][2]);
                    acc[ci][3] = fmaf(kvt.w, win[kw + 3], acc[ci][3]);
                }
            }
        }

        #pragma unroll
        for (int ci = 0; ci < CPT; ci++) {
            float4 o;
            o.x = acc[ci][0]; o.y = acc[ci][1]; o.z = acc[ci][2]; o.w = acc[ci][3];
            *reinterpret_cast<float4*>(ob + (size_t)ci * HW_ + (size_t)s * W_) = o;
        }

        // Rotate: finished prefetched row replaces the retired top slot.
        if (s < HSTRIP - 1) finish_row(nxt, rbuf[s % 3]);
    }
}

extern "C" void kernel_launch(void* const* d_in, const int* in_sizes, int n_in,
                              void* d_out, int out_size)
{
    const float* x   = (const float*)d_in[0];   // [8,256,64,64]
    const float* ker = (const float*)d_in[1];   // [8,1,9,64,64]
    float* out = (float*)d_out;                 // [8,256,64,64]

    dim3 block(16, 16);
    dim3 grid(N_ * (H_ / HSTRIP), C_ / (16 * CPT));
    ddf_kernel<<<grid, block>>>(x, ker, out);
}